// round 1
// baseline (speedup 1.0000x reference)
#include <cuda_runtime.h>

// Problem constants (fixed by the reference: N=16, C=19, H=W=512)
#define NCLS 19
#define NIMG 16
#define HWPX (512 * 512)          // pixels per image = 262144
#define EPSV 1e-6f

// Scratch: per-(image,class) counters. __device__ globals (no allocation).
__device__ unsigned int g_pred [NIMG * NCLS];
__device__ unsigned int g_targ [NIMG * NCLS];
__device__ unsigned int g_inter[NIMG * NCLS];

// ---------------------------------------------------------------------------
// Kernel 1: zero the counters (must run before the histogram kernel).
// ---------------------------------------------------------------------------
__global__ void miou_zero_kernel() {
    int i = threadIdx.x;
    if (i < NIMG * NCLS) {
        g_pred[i]  = 0u;
        g_targ[i]  = 0u;
        g_inter[i] = 0u;
    }
}

// ---------------------------------------------------------------------------
// Kernel 2: per-pixel argmax over C=19 + histogram.
// grid = (HWPX / (256*4), NIMG), block = 256. Each thread owns 4 adjacent
// pixels (one float4 per class plane). Fully unrolled class loop -> ptxas
// front-batches 38 independent float4 LDGs (high MLP, memory-bound).
// ---------------------------------------------------------------------------
__global__ void __launch_bounds__(256)
miou_hist_kernel(const float* __restrict__ preds,
                 const float* __restrict__ targets) {
    __shared__ unsigned int sp[NCLS];
    __shared__ unsigned int st[NCLS];
    __shared__ unsigned int si[NCLS];

    const int t = threadIdx.x;
    if (t < NCLS) { sp[t] = 0u; st[t] = 0u; si[t] = 0u; }
    __syncthreads();

    const int n = blockIdx.y;
    // float4 index within one class plane (HWPX/4 float4s per plane)
    const int idx4 = blockIdx.x * blockDim.x + t;

    const float4* __restrict__ p4 =
        (const float4*)(preds   + (size_t)n * NCLS * HWPX);
    const float4* __restrict__ q4 =
        (const float4*)(targets + (size_t)n * NCLS * HWPX);

    float bpv[4], btv[4];
    int   bpi[4], bti[4];
#pragma unroll
    for (int j = 0; j < 4; j++) {
        bpv[j] = -3.4e38f; btv[j] = -3.4e38f; bpi[j] = 0; bti[j] = 0;
    }

#pragma unroll
    for (int c = 0; c < NCLS; c++) {
        const size_t off = (size_t)c * (HWPX / 4) + idx4;
        float4 pv = p4[off];
        float4 tv = q4[off];
        float pa[4] = {pv.x, pv.y, pv.z, pv.w};
        float ta[4] = {tv.x, tv.y, tv.z, tv.w};
#pragma unroll
        for (int j = 0; j < 4; j++) {
            if (pa[j] > bpv[j]) { bpv[j] = pa[j]; bpi[j] = c; }  // strict > keeps first idx (argmax semantics)
            if (ta[j] > btv[j]) { btv[j] = ta[j]; bti[j] = c; }
        }
    }

#pragma unroll
    for (int j = 0; j < 4; j++) {
        atomicAdd(&sp[bpi[j]], 1u);
        atomicAdd(&st[bti[j]], 1u);
        if (bpi[j] == bti[j]) atomicAdd(&si[bpi[j]], 1u);
    }
    __syncthreads();

    if (t < NCLS) {
        if (sp[t]) atomicAdd(&g_pred [n * NCLS + t], sp[t]);
        if (st[t]) atomicAdd(&g_targ [n * NCLS + t], st[t]);
        if (si[t]) atomicAdd(&g_inter[n * NCLS + t], si[t]);
    }
}

// ---------------------------------------------------------------------------
// Kernel 3: finalize. One block of 512 threads reduces 16*19=304 IoU terms.
// out = mean_n mean_c ( (inter+eps)/(union+eps) * w[c] ) = sum / (N*C)
// ---------------------------------------------------------------------------
__global__ void __launch_bounds__(512)
miou_final_kernel(const float* __restrict__ w, float* __restrict__ out) {
    const int t = threadIdx.x;
    float v = 0.0f;
    if (t < NIMG * NCLS) {
        const int c = t % NCLS;
        float inter = (float)g_inter[t];
        float uni   = (float)g_pred[t] + (float)g_targ[t] - inter;
        v = (inter + EPSV) / (uni + EPSV) * w[c];
    }

    // block reduction: warp shuffle then shared
    __shared__ float warp_sums[16];
#pragma unroll
    for (int o = 16; o > 0; o >>= 1)
        v += __shfl_down_sync(0xFFFFFFFFu, v, o);
    if ((t & 31) == 0) warp_sums[t >> 5] = v;
    __syncthreads();
    if (t < 32) {
        float s = (t < 16) ? warp_sums[t] : 0.0f;
#pragma unroll
        for (int o = 8; o > 0; o >>= 1)
            s += __shfl_down_sync(0xFFFFFFFFu, s, o);
        if (t == 0) out[0] = s / (float)(NIMG * NCLS);
    }
}

// ---------------------------------------------------------------------------
extern "C" void kernel_launch(void* const* d_in, const int* in_sizes, int n_in,
                              void* d_out, int out_size) {
    const float* preds   = (const float*)d_in[0];
    const float* targets = (const float*)d_in[1];
    const float* weights = (const float*)d_in[2];
    float* out = (float*)d_out;

    miou_zero_kernel<<<1, 512>>>();

    // 4 pixels/thread, 256 threads/block -> 1024 pixels/block
    dim3 grid(HWPX / (256 * 4), NIMG);   // (256, 16) = 4096 blocks
    miou_hist_kernel<<<grid, 256>>>(preds, targets);

    miou_final_kernel<<<1, 512>>>(weights, out);
}